// round 10
// baseline (speedup 1.0000x reference)
#include <cuda_runtime.h>

// StrictOrthogonal via Cholesky-QR — SINGLE fused persistent kernel.
//   Phase A: G partials = X^H X slices   (148 blocks, 8 K-groups x 64 thr)
//   Phase B: slice reduce (blocks 0-36) -> Cholesky + W = R^{-1} (block 0)
//   Phase C: Q = X W (register-tiled triangular GEMM, blocks 0-127)
// Inter-block sync: threadfence + atomic counters (all 148 blocks resident ->
// spin is safe). Counters self-reset by the last-finishing block so every
// graph replay starts from identical state. All fp sums fixed-order.

#define MROWS 16384
#define RCOLS 32
#define NBLK  148
#define NTHR  512
#define RPB   111              // ceil(16384/148); last block has 67 rows
#define NSLICE 37              // 37 * 4 = 148 partials

__device__ float2 g_partials[NBLK][1024];
__device__ float2 g_p2[NSLICE][1024];
__device__ float2 g_W[1024];            // W = R^{-1} (upper, zeros below diag)
__device__ int g_cnt_a, g_cnt_b, g_flag_c, g_cnt_d;

__global__ void __launch_bounds__(NTHR) fused_kernel(const float* __restrict__ x,
                                                     float* __restrict__ out) {
    __shared__ __align__(16) char smem_raw[44800];
    const int t = threadIdx.x;
    const int b = blockIdx.x;

    // ===================== Phase A: partial Gram =====================
    {
        float*  s_re = reinterpret_cast<float*>(smem_raw);           // [111*32] 14208B
        float*  s_im = s_re + RPB * RCOLS;                           // 14208B
        float2 (*red)[256] = reinterpret_cast<float2(*)[256]>(s_im + RPB * RCOLS); // [8][256] 16KB

        const int start = b * RPB;
        const int nrows = min(RPB, MROWS - start);
        const float4* __restrict__ xr4 =
            reinterpret_cast<const float4*>(x) + (size_t)start * (RCOLS / 2);

        for (int n = t; n < nrows * (RCOLS / 2); n += NTHR) {
            float4 v = xr4[n];
            s_re[2 * n]     = v.x;  s_im[2 * n]     = v.y;
            s_re[2 * n + 1] = v.z;  s_im[2 * n + 1] = v.w;
        }
        __syncthreads();

        const int g  = t >> 6;          // K-group 0..7 (rows r == g mod 8)
        const int u  = t & 63;
        const int i0 = (u >> 3) * 4;    // 0,4,...,28
        const int j0 = (u & 7) * 4;     // 0,4,...,28

        float accx[4][4], accy[4][4];
        #pragma unroll
        for (int p = 0; p < 4; p++)
            #pragma unroll
            for (int q = 0; q < 4; q++) { accx[p][q] = 0.f; accy[p][q] = 0.f; }

        #pragma unroll 2
        for (int r = g; r < nrows; r += 8) {
            const float* rr = s_re + r * RCOLS;
            const float* ri = s_im + r * RCOLS;
            float4 arx = *reinterpret_cast<const float4*>(rr + i0);
            float4 ary = *reinterpret_cast<const float4*>(ri + i0);
            float4 brx = *reinterpret_cast<const float4*>(rr + j0);
            float4 bry = *reinterpret_cast<const float4*>(ri + j0);
            const float ax[4] = {arx.x, arx.y, arx.z, arx.w};
            const float ay[4] = {ary.x, ary.y, ary.z, ary.w};
            const float bx[4] = {brx.x, brx.y, brx.z, brx.w};
            const float by[4] = {bry.x, bry.y, bry.z, bry.w};
            #pragma unroll
            for (int p = 0; p < 4; p++)
                #pragma unroll
                for (int q = 0; q < 4; q++) {
                    // acc += conj(a_p) * b_q
                    accx[p][q] = fmaf(ax[p], bx[q], accx[p][q]);
                    accx[p][q] = fmaf(ay[p], by[q], accx[p][q]);
                    accy[p][q] = fmaf(ax[p], by[q], accy[p][q]);
                    accy[p][q] = fmaf(-ay[p], bx[q], accy[p][q]);
                }
        }
        __syncthreads();

        // cross-group reduce in 4 passes of 256 entries (rows [8p, 8p+8))
        #pragma unroll 1
        for (int p = 0; p < 4; p++) {
            if ((i0 >> 3) == p) {
                const int il = i0 & 7;                     // 0 or 4
                #pragma unroll
                for (int pp = 0; pp < 4; pp++)
                    #pragma unroll
                    for (int qq = 0; qq < 4; qq++)
                        red[g][(il + pp) * 32 + j0 + qq] =
                            make_float2(accx[pp][qq], accy[pp][qq]);
            }
            __syncthreads();
            if (t < 256) {
                float sx = 0.f, sy = 0.f;
                #pragma unroll
                for (int gg = 0; gg < 8; gg++) {
                    float2 v = red[gg][t];
                    sx += v.x; sy += v.y;
                }
                g_partials[b][p * 256 + t] = make_float2(sx, sy);
            }
            __syncthreads();
        }
    }

    // ===================== sync 1: all partials ready =====================
    __threadfence();
    __syncthreads();
    if (t == 0) atomicAdd(&g_cnt_a, 1);

    // ===================== Phase B1: slice reduce (blocks 0..36) ==========
    if (b < NSLICE) {
        if (t == 0) { while (atomicAdd(&g_cnt_a, 0) < NBLK) { } }
        __syncthreads();
        const int b0 = b * 4;
        float4 s = reinterpret_cast<const float4*>(g_partials[b0])[t];
        #pragma unroll
        for (int k = 1; k < 4; k++) {
            float4 p = reinterpret_cast<const float4*>(g_partials[b0 + k])[t];
            s.x += p.x; s.y += p.y; s.z += p.z; s.w += p.w;
        }
        reinterpret_cast<float4*>(g_p2[b])[t] = s;
        __threadfence();
        __syncthreads();
        if (t == 0) atomicAdd(&g_cnt_b, 1);
    }

    // ===================== Phase B2: Cholesky + W (block 0) ===============
    if (b == 0) {
        if (t == 0) { while (atomicAdd(&g_cnt_b, 0) < NSLICE) { } }
        __syncthreads();

        float2 (*Gs)[RCOLS + 1] = reinterpret_cast<float2(*)[RCOLS + 1]>(smem_raw);          // 8448B
        float2 (*Rs)[RCOLS]     = reinterpret_cast<float2(*)[RCOLS]>(smem_raw + 8448);       // 8192B
        float2 (*Bs)[RCOLS + 1] = reinterpret_cast<float2(*)[RCOLS + 1]>(smem_raw + 16640);  // 8448B

        const int i  = t >> 4;          // 0..31
        const int jc0 = 2 * (t & 15);   // even col
        const int jc1 = jc0 + 1;        // odd col

        // final reduce of 37 slices; thread t holds entries (i, jc0) and (i, jc1)
        {
            float4 s = reinterpret_cast<const float4*>(g_p2[0])[t];
            #pragma unroll 4
            for (int k = 1; k < NSLICE; k++) {
                float4 p = reinterpret_cast<const float4*>(g_p2[k])[t];
                s.x += p.x; s.y += p.y; s.z += p.z; s.w += p.w;
            }
            Gs[i][jc0] = make_float2(s.x, s.y);
            Gs[i][jc1] = make_float2(s.z, s.w);
            Bs[i][jc0] = make_float2((i == jc0) ? 1.f : 0.f, 0.f);
            Bs[i][jc1] = make_float2((i == jc1) ? 1.f : 0.f, 0.f);
        }
        __syncthreads();

        // sqrt-free Cholesky (lower triangle), 1 barrier per step
        #pragma unroll 1
        for (int k = 0; k < RCOLS; k++) {
            const float invg = 1.f / Gs[k][k].x;
            if (i > k) {
                float2 a = Gs[i][k];
                if (jc0 > k && jc0 <= i) {
                    float2 c = Gs[jc0][k];
                    Gs[i][jc0].x -= (a.x * c.x + a.y * c.y) * invg;
                    Gs[i][jc0].y -= (a.y * c.x - a.x * c.y) * invg;
                }
                if (jc1 > k && jc1 <= i) {
                    float2 c = Gs[jc1][k];
                    Gs[i][jc1].x -= (a.x * c.x + a.y * c.y) * invg;
                    Gs[i][jc1].y -= (a.y * c.x - a.x * c.y) * invg;
                }
            }
            __syncthreads();
        }

        // build R (upper): R[i][j] = conj(Gs[j][i]) * rsqrt(D_i), R[i][i] = sqrt(D_i)
        {
            const float s = rsqrtf(Gs[i][i].x);
            float2 r0 = make_float2(0.f, 0.f), r1 = make_float2(0.f, 0.f);
            if (jc0 > i)       { float2 l = Gs[jc0][i]; r0 = make_float2(l.x * s, -l.y * s); }
            else if (jc0 == i) { r0 = make_float2(sqrtf(Gs[i][i].x), 0.f); }
            if (jc1 > i)       { float2 l = Gs[jc1][i]; r1 = make_float2(l.x * s, -l.y * s); }
            else if (jc1 == i) { r1 = make_float2(sqrtf(Gs[i][i].x), 0.f); }
            Rs[i][jc0] = r0;
            Rs[i][jc1] = r1;
        }
        __syncthreads();

        // back-substitution: R W = I, 1 barrier per step
        #pragma unroll 1
        for (int k = RCOLS - 1; k >= 0; k--) {
            const float inv = 1.f / Rs[k][k].x;
            float2 b0v = Bs[k][jc0], b1v = Bs[k][jc1];
            float2 w0 = make_float2(b0v.x * inv, b0v.y * inv);
            float2 w1 = make_float2(b1v.x * inv, b1v.y * inv);
            if (i == k) {
                g_W[k * RCOLS + jc0] = (jc0 >= k) ? w0 : make_float2(0.f, 0.f);
                g_W[k * RCOLS + jc1] = (jc1 >= k) ? w1 : make_float2(0.f, 0.f);
            }
            if (i < k) {
                float2 r = Rs[i][k];
                Bs[i][jc0].x -= r.x * w0.x - r.y * w0.y;
                Bs[i][jc0].y -= r.x * w0.y + r.y * w0.x;
                Bs[i][jc1].x -= r.x * w1.x - r.y * w1.y;
                Bs[i][jc1].y -= r.x * w1.y + r.y * w1.x;
            }
            __syncthreads();
        }

        __threadfence();
        __syncthreads();
        if (t == 0) atomicExch(&g_flag_c, 1);
    }

    // ===================== sync 3 + Phase C: apply ========================
    if (t == 0) { while (atomicAdd(&g_flag_c, 0) == 0) { } }
    __syncthreads();

    if (b < MROWS / 128) {            // 128 tiles of 128 rows
        float2 (*Ws)[RCOLS]     = reinterpret_cast<float2(*)[RCOLS]>(smem_raw);         // 8192B
        float2 (*Xs)[RCOLS + 1] = reinterpret_cast<float2(*)[RCOLS + 1]>(smem_raw + 8192); // 33792B

        #pragma unroll
        for (int l = 0; l < 2; l++) {
            const int e = t + NTHR * l;
            Ws[e >> 5][e & 31] = g_W[e];
        }
        const int rowbase = b * 128;
        const float4* __restrict__ src =
            reinterpret_cast<const float4*>(x) + (size_t)rowbase * (RCOLS / 2);
        #pragma unroll
        for (int l = 0; l < 4; l++) {
            const int n = t + NTHR * l;          // 0..2047
            const int r = n >> 4, q = n & 15;
            float4 f = src[n];
            Xs[r][2 * q]     = make_float2(f.x, f.y);
            Xs[r][2 * q + 1] = make_float2(f.z, f.w);
        }
        __syncthreads();

        const int r  = t & 63;          // rows r and r+64
        const int c  = t >> 6;          // column group 0..7
        const int j0 = 4 * c;

        float ax[2][4], ay[2][4];
        #pragma unroll
        for (int m = 0; m < 4; m++) {
            ax[0][m] = 0.f; ay[0][m] = 0.f;
            ax[1][m] = 0.f; ay[1][m] = 0.f;
        }

        #pragma unroll 1
        for (int ch = 0; ch <= c; ch++) {          // triangular: ii < 4c+4
            #pragma unroll
            for (int k = 0; k < 4; k++) {
                const int ii = 4 * ch + k;
                const float2 a0 = Xs[r][ii];
                const float2 a1 = Xs[r + 64][ii];
                const float4 w01 = *reinterpret_cast<const float4*>(&Ws[ii][j0]);
                const float4 w23 = *reinterpret_cast<const float4*>(&Ws[ii][j0 + 2]);
                const float wx[4] = {w01.x, w01.z, w23.x, w23.z};
                const float wy[4] = {w01.y, w01.w, w23.y, w23.w};
                #pragma unroll
                for (int m = 0; m < 4; m++) {
                    ax[0][m] = fmaf(a0.x, wx[m], ax[0][m]); ax[0][m] = fmaf(-a0.y, wy[m], ax[0][m]);
                    ay[0][m] = fmaf(a0.x, wy[m], ay[0][m]); ay[0][m] = fmaf( a0.y, wx[m], ay[0][m]);
                    ax[1][m] = fmaf(a1.x, wx[m], ax[1][m]); ax[1][m] = fmaf(-a1.y, wy[m], ax[1][m]);
                    ay[1][m] = fmaf(a1.x, wy[m], ay[1][m]); ay[1][m] = fmaf( a1.y, wx[m], ay[1][m]);
                }
            }
        }

        float4* __restrict__ dst0 =
            reinterpret_cast<float4*>(out) + (size_t)(rowbase + r) * (RCOLS / 2) + 2 * c;
        float4* __restrict__ dst1 =
            reinterpret_cast<float4*>(out) + (size_t)(rowbase + r + 64) * (RCOLS / 2) + 2 * c;
        dst0[0] = make_float4(ax[0][0], ay[0][0], ax[0][1], ay[0][1]);
        dst0[1] = make_float4(ax[0][2], ay[0][2], ax[0][3], ay[0][3]);
        dst1[0] = make_float4(ax[1][0], ay[1][0], ax[1][1], ay[1][1]);
        dst1[1] = make_float4(ax[1][2], ay[1][2], ax[1][3], ay[1][3]);
    }

    // ===================== self-reset (last block) ========================
    if (t == 0) {
        int old = atomicAdd(&g_cnt_d, 1);
        if (old == NBLK - 1) {            // everyone has passed all gates
            atomicExch(&g_cnt_a, 0);
            atomicExch(&g_cnt_b, 0);
            atomicExch(&g_flag_c, 0);
            atomicExch(&g_cnt_d, 0);
        }
    }
}

// ---------------------------------------------------------------------------
extern "C" void kernel_launch(void* const* d_in, const int* in_sizes, int n_in,
                              void* d_out, int out_size) {
    const float* x = (const float*)d_in[0];
    float* out = (float*)d_out;
    fused_kernel<<<NBLK, NTHR>>>(x, out);
}